// round 11
// baseline (speedup 1.0000x reference)
#include <cuda_runtime.h>
#include <cuda_fp16.h>
#include <cstdint>
#include <cstddef>

// ---------------------------------------------------------------------------
#define NBAT 4
#define SEQL 2048
#define EMB  1024
#define MQ   (NBAT * SEQL)   /* 8192 */

static constexpr size_t EX = (size_t)MQ * EMB;
static constexpr size_t EW = (size_t)EMB * EMB;
static constexpr size_t EP = (size_t)NBAT * SEQL * SEQL;

// Scratch (__device__ statics)
__device__ __half g_xvh[EX], g_xvl[EX];   // values split (B of V-proj)
__device__ __half g_xkh[EX];              // keys hi (A of K-proj)
__device__ __half g_xqh[EX];              // query hi (A of Q-proj)
__device__ __half g_wvh[EW], g_wvl[EW];
__device__ __half g_wkh[EW], g_wkl[EW];
__device__ __half g_wqh[EW], g_wql[EW];
__device__ __half g_woh[EW], g_wol[EW];
__device__ __half g_qh[EX];               // projected Q (hi only)
__device__ __half g_kh[EX],  g_kl[EX];    // projected K split
__device__ __half g_vth[EX], g_vtl[EX];   // projected V split, [b][emb][seq]
__device__ float  g_e[EP];
__device__ __half g_ph[EP];               // softmax probs (hi only)
__device__ __half g_oh[EX];               // attn @ V (hi only)

// ---------------------------------------------------------------------------
__device__ __forceinline__ uint32_t smem_u32(const void* p) {
    uint32_t a;
    asm("{ .reg .u64 t; cvta.to.shared.u64 t, %1; cvt.u32.u64 %0, t; }" : "=r"(a) : "l"(p));
    return a;
}
__device__ __forceinline__ void cp16(uint32_t s, const void* g) {
    asm volatile("cp.async.cg.shared.global [%0], [%1], 16;" :: "r"(s), "l"(g) : "memory");
}
#define CP_COMMIT() asm volatile("cp.async.commit_group;" ::: "memory")

__device__ __forceinline__ void ldsm4(uint32_t* r, uint32_t addr) {
    asm volatile("ldmatrix.sync.aligned.m8n8.x4.shared.b16 {%0,%1,%2,%3}, [%4];"
        : "=r"(r[0]), "=r"(r[1]), "=r"(r[2]), "=r"(r[3]) : "r"(addr));
}
// fp32-accumulator HMMA (hi term)
__device__ __forceinline__ void mma16816(float* c, const uint32_t* a, const uint32_t* b) {
    asm volatile("mma.sync.aligned.m16n8k16.row.col.f32.f16.f16.f32 "
        "{%0,%1,%2,%3}, {%4,%5,%6,%7}, {%8,%9}, {%0,%1,%2,%3};"
        : "+f"(c[0]), "+f"(c[1]), "+f"(c[2]), "+f"(c[3])
        : "r"(a[0]), "r"(a[1]), "r"(a[2]), "r"(a[3]), "r"(b[0]), "r"(b[1]));
}
// fp16-accumulator HMMA (lo term; magnitudes ~2^-11 of C, fp16 acc is safe)
__device__ __forceinline__ void mma16816h(uint32_t* c, const uint32_t* a, const uint32_t* b) {
    asm volatile("mma.sync.aligned.m16n8k16.row.col.f16.f16.f16.f16 "
        "{%0,%1}, {%2,%3,%4,%5}, {%6,%7}, {%0,%1};"
        : "+r"(c[0]), "+r"(c[1])
        : "r"(a[0]), "r"(a[1]), "r"(a[2]), "r"(a[3]), "r"(b[0]), "r"(b[1]));
}

__device__ __forceinline__ void split2(float f0, float f1, uint32_t& hi, uint32_t& lo) {
    __half h0 = __float2half_rn(f0), h1 = __float2half_rn(f1);
    __half l0 = __float2half_rn(f0 - __half2float(h0));
    __half l1 = __float2half_rn(f1 - __half2float(h1));
    hi = (uint32_t)__half_as_ushort(h0) | ((uint32_t)__half_as_ushort(h1) << 16);
    lo = (uint32_t)__half_as_ushort(l0) | ((uint32_t)__half_as_ushort(l1) << 16);
}
__device__ __forceinline__ uint32_t pack2(float f0, float f1) {
    return (uint32_t)__half_as_ushort(__float2half_rn(f0))
         | ((uint32_t)__half_as_ushort(__float2half_rn(f1)) << 16);
}

// ---------------------------------------------------------------------------
// 2-term split HGEMM:  C = Ah*Bh^T (fp32 acc) + Ah*Bl^T (fp16 acc, promoted)
// A,B K-major [rows][K]. CTA tile 128x128, 256 thr, warp tile 64x32,
// K-chunks of 32, 3-stage cp.async (wait_group 1).
// smem rows padded to 80B -> conflict-free ldmatrix.
// MODE: 0 fp32 | 1 split fp16 | 2 fp32+bias | 3 split fp16 batch-folded (V)
//       4 fp16 hi-only
// ---------------------------------------------------------------------------
#define TILE_B 10240               /* 128 rows * 80 B */
#define STG_B  (3 * TILE_B)        /* Ah, Bh, Bl */
#define STAGES 3
#define GEMM_SMEM (STAGES * STG_B) /* 92160 */

template <int MODE>
__global__ __launch_bounds__(256)
void hgemm(const __half* __restrict__ Ah,
           const __half* __restrict__ Bh, const __half* __restrict__ Bl,
           int K, size_t sA, size_t sB,
           float* __restrict__ Cf, const float* __restrict__ bias,
           size_t sC, int Nc,
           __half* __restrict__ Ch, __half* __restrict__ Cl)
{
    extern __shared__ char smc[];
    const uint32_t sb = smem_u32(smc);
    const int tid = threadIdx.x, lane = tid & 31, wid = tid >> 5;
    const int m0 = blockIdx.y * 128, n0 = blockIdx.x * 128, b = blockIdx.z;
    const int nch = K >> 5;

    const __half* srcs[3];
    srcs[0] = Ah + (size_t)b * sA + (size_t)m0 * K;
    srcs[1] = Bh + (size_t)b * sB + (size_t)n0 * K;
    srcs[2] = Bl + (size_t)b * sB + (size_t)n0 * K;

    // producer: 1536 cp16 per stage / 256 thr = 6 each
    auto load_stage = [&](int s, int chunk) {
        const uint32_t dbase = sb + s * STG_B;
        const int k0 = chunk * 32;
        #pragma unroll
        for (int i = 0; i < 6; i++) {
            const int cid = tid + i * 256;
            const int tile = cid >> 9, r = (cid >> 2) & 127, seg = cid & 3;
            cp16(dbase + tile * TILE_B + r * 80 + seg * 16,
                 srcs[tile] + (size_t)r * K + k0 + seg * 8);
        }
    };

    load_stage(0, 0);
    CP_COMMIT();
    load_stage(1, 1);
    CP_COMMIT();

    const int m0w = (wid >> 2) * 64, n0w = (wid & 3) * 32;
    const uint32_t aoff = (uint32_t)(m0w + (lane & 15)) * 80 + ((lane >> 4) * 16);
    const uint32_t boff = (uint32_t)(n0w + ((lane >> 4) & 1) * 8 + (lane & 7)) * 80
                        + (((lane >> 3) & 1) * 16);

    float acc[4][4][4];
    uint32_t accl[4][4][2];            // fp16 lo-term accumulators
    #pragma unroll
    for (int a = 0; a < 4; a++)
        #pragma unroll
        for (int c = 0; c < 4; c++) {
            #pragma unroll
            for (int d = 0; d < 4; d++) acc[a][c][d] = 0.f;
            accl[a][c][0] = 0u; accl[a][c][1] = 0u;
        }

    for (int c = 0; c < nch; c++) {
        asm volatile("cp.async.wait_group 1;" ::: "memory");
        __syncthreads();
        if (c + 2 < nch) { load_stage((c + 2) % STAGES, c + 2); CP_COMMIT(); }

        const uint32_t st = sb + (c % STAGES) * STG_B;
        const uint32_t aH = st + aoff;
        const uint32_t bH = st + TILE_B + boff, bL = st + 2 * TILE_B + boff;

        #pragma unroll
        for (int ks = 0; ks < 2; ks++) {
            uint32_t ah[4][4], bh[4][2], bl[4][2];
            #pragma unroll
            for (int mi = 0; mi < 4; mi++)
                ldsm4(ah[mi], aH + mi * 1280 + ks * 32);
            #pragma unroll
            for (int j = 0; j < 2; j++) {
                uint32_t t[4];
                ldsm4(t, bH + j * 1280 + ks * 32);
                bh[2*j][0] = t[0]; bh[2*j][1] = t[1];
                bh[2*j+1][0] = t[2]; bh[2*j+1][1] = t[3];
                ldsm4(t, bL + j * 1280 + ks * 32);
                bl[2*j][0] = t[0]; bl[2*j][1] = t[1];
                bl[2*j+1][0] = t[2]; bl[2*j+1][1] = t[3];
            }
            // hi term: fp32 acc; lo term: fp16 acc (half-size instruction)
            #pragma unroll
            for (int mi = 0; mi < 4; mi++)
                #pragma unroll
                for (int ni = 0; ni < 4; ni++)
                    mma16816(acc[mi][ni], ah[mi], bh[ni]);
            #pragma unroll
            for (int mi = 0; mi < 4; mi++)
                #pragma unroll
                for (int ni = 0; ni < 4; ni++)
                    mma16816h(accl[mi][ni], ah[mi], bl[ni]);
        }
    }

    // promote fp16 lo accumulators into fp32
    #pragma unroll
    for (int mi = 0; mi < 4; mi++)
        #pragma unroll
        for (int ni = 0; ni < 4; ni++) {
            __half2 h0 = *reinterpret_cast<__half2*>(&accl[mi][ni][0]);
            __half2 h1 = *reinterpret_cast<__half2*>(&accl[mi][ni][1]);
            acc[mi][ni][0] += __low2float(h0);
            acc[mi][ni][1] += __high2float(h0);
            acc[mi][ni][2] += __low2float(h1);
            acc[mi][ni][3] += __high2float(h1);
        }

    const int fr = lane >> 2, fc = (lane & 3) * 2;
    #pragma unroll
    for (int mi = 0; mi < 4; mi++)
        #pragma unroll
        for (int ni = 0; ni < 4; ni++) {
            const int row = m0 + m0w + mi * 16 + fr;
            const int col = n0 + n0w + ni * 8 + fc;
            float* pc = acc[mi][ni];
            if (MODE == 0 || MODE == 2) {
                float2 v0 = make_float2(pc[0], pc[1]);
                float2 v1 = make_float2(pc[2], pc[3]);
                if (MODE == 2) {
                    const float b0v = bias[col], b1v = bias[col + 1];
                    v0.x += b0v; v0.y += b1v; v1.x += b0v; v1.y += b1v;
                }
                float* base = Cf + (size_t)b * sC;
                *(float2*)(base + (size_t)row * Nc + col) = v0;
                *(float2*)(base + (size_t)(row + 8) * Nc + col) = v1;
            } else if (MODE == 1) {
                uint32_t h0, l0, h1, l1;
                split2(pc[0], pc[1], h0, l0);
                split2(pc[2], pc[3], h1, l1);
                const size_t i0 = (size_t)b * sC + (size_t)row * Nc + col;
                const size_t i1 = (size_t)b * sC + (size_t)(row + 8) * Nc + col;
                *(uint32_t*)(Ch + i0) = h0; *(uint32_t*)(Cl + i0) = l0;
                *(uint32_t*)(Ch + i1) = h1; *(uint32_t*)(Cl + i1) = l1;
            } else if (MODE == 3) {
                uint32_t h0, l0, h1, l1;
                split2(pc[0], pc[1], h0, l0);
                split2(pc[2], pc[3], h1, l1);
                const size_t bb = (size_t)(col >> 11) * ((size_t)EMB * SEQL);
                const size_t i0 = bb + (size_t)row * SEQL + (col & 2047);
                const size_t i1 = i0 + (size_t)8 * SEQL;
                *(uint32_t*)(Ch + i0) = h0; *(uint32_t*)(Cl + i0) = l0;
                *(uint32_t*)(Ch + i1) = h1; *(uint32_t*)(Cl + i1) = l1;
            } else {
                const size_t i0 = (size_t)b * sC + (size_t)row * Nc + col;
                const size_t i1 = (size_t)b * sC + (size_t)(row + 8) * Nc + col;
                *(uint32_t*)(Ch + i0) = pack2(pc[0], pc[1]);
                *(uint32_t*)(Ch + i1) = pack2(pc[2], pc[3]);
            }
        }
}

// ---------------------------------------------------------------------------
// fp32 -> fp16 hi/lo split; up to 4 arrays per launch (blockIdx.y selects)
// ---------------------------------------------------------------------------
struct SplitJob { const float* x; __half* h; __half* l; };

__global__ __launch_bounds__(256)
void split_multi(SplitJob j0, SplitJob j1, SplitJob j2, SplitJob j3, int n4)
{
    const SplitJob& j = (blockIdx.y == 0) ? j0 : (blockIdx.y == 1) ? j1
                      : (blockIdx.y == 2) ? j2 : j3;
    int i = blockIdx.x * 256 + threadIdx.x;
    if (i >= n4) return;
    float4 v = ((const float4*)j.x)[i];
    uint32_t h0, l0, h1, l1;
    split2(v.x, v.y, h0, l0);
    split2(v.z, v.w, h1, l1);
    ((uint2*)j.h)[i] = make_uint2(h0, h1);
    ((uint2*)j.l)[i] = make_uint2(l0, l1);
}

// fp32 -> fp16 convert (hi only); 2 arrays per launch
__global__ __launch_bounds__(256)
void convert2(const float* __restrict__ x0, __half* __restrict__ h0p,
              const float* __restrict__ x1, __half* __restrict__ h1p, int n4)
{
    const float* x = blockIdx.y ? x1 : x0;
    __half* h = blockIdx.y ? h1p : h0p;
    int i = blockIdx.x * 256 + threadIdx.x;
    if (i >= n4) return;
    float4 v = ((const float4*)x)[i];
    ((uint2*)h)[i] = make_uint2(pack2(v.x, v.y), pack2(v.z, v.w));
}

// ---------------------------------------------------------------------------
// masked softmax on fp32 E, writing fp16 (hi only) probabilities
// ---------------------------------------------------------------------------
__global__ __launch_bounds__(256)
void softmax_h(const float* __restrict__ E, const int* __restrict__ mask,
               __half* __restrict__ Ph)
{
    const int row = blockIdx.x;
    const int b = row >> 11;
    const float* e = E + (size_t)row * SEQL;
    const int* m = mask + (size_t)b * SEQL * SEQL + (size_t)(row & 2047) * SEQL;
    const int t = threadIdx.x;
    const int base = t * 8;

    float v[8];
    #pragma unroll
    for (int g = 0; g < 2; g++) {
        float4 ev = *(const float4*)(e + base + g * 4);
        int4 mv = *(const int4*)(m + base + g * 4);
        v[g*4+0] = ((mv.x == 0) ? -1e20f : ev.x) * 0.03125f;
        v[g*4+1] = ((mv.y == 0) ? -1e20f : ev.y) * 0.03125f;
        v[g*4+2] = ((mv.z == 0) ? -1e20f : ev.z) * 0.03125f;
        v[g*4+3] = ((mv.w == 0) ? -1e20f : ev.w) * 0.03125f;
    }
    float mx = -3.4e38f;
    #pragma unroll
    for (int i = 0; i < 8; i++) mx = fmaxf(mx, v[i]);

    __shared__ float red[256];
    red[t] = mx;
    __syncthreads();
    for (int s = 128; s > 0; s >>= 1) {
        if (t < s) red[t] = fmaxf(red[t], red[t + s]);
        __syncthreads();
    }
    mx = red[0];
    __syncthreads();

    float sum = 0.f;
    #pragma unroll
    for (int i = 0; i < 8; i++) { v[i] = __expf(v[i] - mx); sum += v[i]; }
    red[t] = sum;
    __syncthreads();
    for (int s = 128; s > 0; s >>= 1) {
        if (t < s) red[t] += red[t + s];
        __syncthreads();
    }
    const float inv = 1.f / red[0];

    #pragma unroll
    for (int g = 0; g < 2; g++) {
        uint2 hv;
        hv.x = pack2(v[g*4+0] * inv, v[g*4+1] * inv);
        hv.y = pack2(v[g*4+2] * inv, v[g*4+3] * inv);
        ((uint2*)(Ph + (size_t)row * SEQL + base))[g] = hv;
    }
}

// ---------------------------------------------------------------------------
#define SYM(p, s) do { void* _t; cudaGetSymbolAddress(&_t, s); p = (decltype(p))_t; } while (0)

extern "C" void kernel_launch(void* const* d_in, const int* in_sizes, int n_in,
                              void* d_out, int out_size)
{
    const float* values = (const float*)d_in[0];
    const float* keys   = (const float*)d_in[1];
    const float* query  = (const float*)d_in[2];
    const int*   mask   = (const int*)  d_in[3];
    const float* Wv     = (const float*)d_in[4];
    const float* Wk     = (const float*)d_in[5];
    const float* Wq     = (const float*)d_in[6];
    const float* Wo     = (const float*)d_in[7];
    const float* bo     = (const float*)d_in[8];
    float* out = (float*)d_out;

    __half *xvh, *xvl, *xkh, *xqh;
    __half *wvh, *wvl, *wkh, *wkl, *wqh, *wql, *woh, *wol;
    __half *qh, *kh, *kl, *vth, *vtl, *ph, *oh;
    float* ge;
    SYM(xvh, g_xvh); SYM(xvl, g_xvl); SYM(xkh, g_xkh); SYM(xqh, g_xqh);
    SYM(wvh, g_wvh); SYM(wvl, g_wvl); SYM(wkh, g_wkh); SYM(wkl, g_wkl);
    SYM(wqh, g_wqh); SYM(wql, g_wql); SYM(woh, g_woh); SYM(wol, g_wol);
    SYM(qh, g_qh); SYM(kh, g_kh); SYM(kl, g_kl);
    SYM(vth, g_vth); SYM(vtl, g_vtl); SYM(ph, g_ph);
    SYM(oh, g_oh); SYM(ge, g_e);

    cudaFuncSetAttribute(hgemm<0>, cudaFuncAttributeMaxDynamicSharedMemorySize, GEMM_SMEM);
    cudaFuncSetAttribute(hgemm<1>, cudaFuncAttributeMaxDynamicSharedMemorySize, GEMM_SMEM);
    cudaFuncSetAttribute(hgemm<2>, cudaFuncAttributeMaxDynamicSharedMemorySize, GEMM_SMEM);
    cudaFuncSetAttribute(hgemm<3>, cudaFuncAttributeMaxDynamicSharedMemorySize, GEMM_SMEM);
    cudaFuncSetAttribute(hgemm<4>, cudaFuncAttributeMaxDynamicSharedMemorySize, GEMM_SMEM);

    const int n4x = (int)(EX / 4), n4w = (int)(EW / 4);
    {
        SplitJob jv{values, xvh, xvl};
        split_multi<<<dim3((n4x + 255) / 256, 1, 1), 256>>>(jv, jv, jv, jv, n4x);
        SplitJob wv{Wv, wvh, wvl}, wk{Wk, wkh, wkl}, wq{Wq, wqh, wql}, wo{Wo, woh, wol};
        split_multi<<<dim3((n4w + 255) / 256, 4, 1), 256>>>(wv, wk, wq, wo, n4w);
        convert2<<<dim3((n4x + 255) / 256, 2, 1), 256>>>(keys, xkh, query, xqh, n4x);
    }

    // Q = Xq @ Wq^T  (hi-only out)
    hgemm<4><<<dim3(8, 64, 1), 256, GEMM_SMEM>>>(
        xqh, wqh, wql, EMB, 0, 0, nullptr, nullptr, 0, EMB, qh, nullptr);
    // K = Xk @ Wk^T  (split out)
    hgemm<1><<<dim3(8, 64, 1), 256, GEMM_SMEM>>>(
        xkh, wkh, wkl, EMB, 0, 0, nullptr, nullptr, 0, EMB, kh, kl);
    // Vt = Wv @ Xv^T (split out, batch-folded transposed layout)
    hgemm<3><<<dim3(64, 8, 1), 256, GEMM_SMEM>>>(
        wvh, xvh, xvl, EMB, 0, 0, nullptr, nullptr, 0, SEQL, vth, vtl);

    // E = Qh @ (Kh+Kl)^T per batch (fp32)
    hgemm<0><<<dim3(16, 16, NBAT), 256, GEMM_SMEM>>>(
        qh, kh, kl, EMB, (size_t)SEQL * EMB, (size_t)SEQL * EMB,
        ge, nullptr, (size_t)SEQL * SEQL, SEQL, nullptr, nullptr);

    softmax_h<<<NBAT * SEQL, 256>>>(ge, mask, ph);

    // O = Ph @ (Vth+Vtl)^T per batch (hi-only out)
    hgemm<4><<<dim3(8, 16, NBAT), 256, GEMM_SMEM>>>(
        ph, vth, vtl, SEQL, (size_t)SEQL * SEQL, (size_t)EMB * SEQL,
        nullptr, nullptr, (size_t)SEQL * EMB, EMB, oh, nullptr);

    // out = Oh @ (Woh+Wol)^T + bo (fp32)
    hgemm<2><<<dim3(8, 64, 1), 256, GEMM_SMEM>>>(
        oh, woh, wol, EMB, 0, 0, out, bo, 0, EMB, nullptr, nullptr);
}

// round 12
// speedup vs baseline: 2.0725x; 2.0725x over previous
#include <cuda_runtime.h>
#include <cuda_fp16.h>
#include <cstdint>
#include <cstddef>

// ---------------------------------------------------------------------------
#define NBAT 4
#define SEQL 2048
#define EMB  1024
#define MQ   (NBAT * SEQL)   /* 8192 */

static constexpr size_t EX = (size_t)MQ * EMB;
static constexpr size_t EW = (size_t)EMB * EMB;
static constexpr size_t EP = (size_t)NBAT * SEQL * SEQL;

// Scratch (__device__ statics) — plain fp16 pipeline
__device__ __half g_xvh[EX];              // values fp16 (B of V-proj)
__device__ __half g_xkh[EX];              // keys fp16
__device__ __half g_xqh[EX];              // query fp16
__device__ __half g_wvh[EW], g_wkh[EW], g_wqh[EW], g_woh[EW];
__device__ __half g_qh[EX];               // projected Q
__device__ __half g_kh[EX];               // projected K
__device__ __half g_vth[EX];              // projected V, [b][emb][seq]
__device__ float  g_e[EP];                // energy fp32
__device__ __half g_ph[EP];               // softmax probs
__device__ __half g_oh[EX];               // attn @ V

// ---------------------------------------------------------------------------
__device__ __forceinline__ uint32_t smem_u32(const void* p) {
    uint32_t a;
    asm("{ .reg .u64 t; cvta.to.shared.u64 t, %1; cvt.u32.u64 %0, t; }" : "=r"(a) : "l"(p));
    return a;
}
__device__ __forceinline__ void cp16(uint32_t s, const void* g) {
    asm volatile("cp.async.cg.shared.global [%0], [%1], 16;" :: "r"(s), "l"(g) : "memory");
}
#define CP_COMMIT() asm volatile("cp.async.commit_group;" ::: "memory")

__device__ __forceinline__ void ldsm4(uint32_t* r, uint32_t addr) {
    asm volatile("ldmatrix.sync.aligned.m8n8.x4.shared.b16 {%0,%1,%2,%3}, [%4];"
        : "=r"(r[0]), "=r"(r[1]), "=r"(r[2]), "=r"(r[3]) : "r"(addr));
}
__device__ __forceinline__ void mma16816(float* c, const uint32_t* a, const uint32_t* b) {
    asm volatile("mma.sync.aligned.m16n8k16.row.col.f32.f16.f16.f32 "
        "{%0,%1,%2,%3}, {%4,%5,%6,%7}, {%8,%9}, {%0,%1,%2,%3};"
        : "+f"(c[0]), "+f"(c[1]), "+f"(c[2]), "+f"(c[3])
        : "r"(a[0]), "r"(a[1]), "r"(a[2]), "r"(a[3]), "r"(b[0]), "r"(b[1]));
}
__device__ __forceinline__ uint32_t pack2(float f0, float f1) {
    return (uint32_t)__half_as_ushort(__float2half_rn(f0))
         | ((uint32_t)__half_as_ushort(__float2half_rn(f1)) << 16);
}

// ---------------------------------------------------------------------------
// Plain fp16 HGEMM:  C = A*B^T  (fp32 accumulate)
// A,B K-major [rows][K]. CTA tile 128x128, 128 thr / 4 warps,
// warp tile 64x64, K-chunks of 32, 3-stage cp.async (wait_group 1).
// smem rows padded to 80B -> conflict-free ldmatrix. 2 CTAs/SM.
// MODE: 0 fp32 | 2 fp32+bias | 4 fp16 | 5 fp16 batch-folded transposed (V)
// ---------------------------------------------------------------------------
#define TILE_B 10240               /* 128 rows * 80 B */
#define STG_B  (2 * TILE_B)        /* A, B */
#define STAGES 3
#define GEMM_SMEM (STAGES * STG_B) /* 61440 */

template <int MODE>
__global__ __launch_bounds__(128, 2)
void hgemm(const __half* __restrict__ Ah, const __half* __restrict__ Bh,
           int K, size_t sA, size_t sB,
           float* __restrict__ Cf, const float* __restrict__ bias,
           size_t sC, int Nc, __half* __restrict__ Ch)
{
    extern __shared__ char smc[];
    const uint32_t sb = smem_u32(smc);
    const int tid = threadIdx.x, lane = tid & 31, wid = tid >> 5;
    const int m0 = blockIdx.y * 128, n0 = blockIdx.x * 128, b = blockIdx.z;
    const int nch = K >> 5;

    const __half* srcA = Ah + (size_t)b * sA + (size_t)m0 * K;
    const __half* srcB = Bh + (size_t)b * sB + (size_t)n0 * K;

    // producer: 1024 cp16 per stage / 128 thr = 8 each
    auto load_stage = [&](int s, int chunk) {
        const uint32_t dbase = sb + s * STG_B;
        const int k0 = chunk * 32;
        #pragma unroll
        for (int i = 0; i < 8; i++) {
            const int cid = tid + i * 128;
            const int tile = cid >> 9, r = (cid >> 2) & 127, seg = cid & 3;
            const __half* src = tile ? srcB : srcA;
            cp16(dbase + tile * TILE_B + r * 80 + seg * 16,
                 src + (size_t)r * K + k0 + seg * 8);
        }
    };

    load_stage(0, 0);
    CP_COMMIT();
    load_stage(1, 1);
    CP_COMMIT();

    const int m0w = (wid >> 1) * 64, n0w = (wid & 1) * 64;
    const uint32_t aoff = (uint32_t)(m0w + (lane & 15)) * 80 + ((lane >> 4) * 16);
    const uint32_t boff = (uint32_t)(n0w + ((lane >> 4) & 1) * 8 + (lane & 7)) * 80
                        + (((lane >> 3) & 1) * 16);

    float acc[4][8][4];
    #pragma unroll
    for (int a = 0; a < 4; a++)
        #pragma unroll
        for (int c = 0; c < 8; c++)
            #pragma unroll
            for (int d = 0; d < 4; d++) acc[a][c][d] = 0.f;

    for (int c = 0; c < nch; c++) {
        asm volatile("cp.async.wait_group 1;" ::: "memory");
        __syncthreads();
        if (c + 2 < nch) { load_stage((c + 2) % STAGES, c + 2); CP_COMMIT(); }

        const uint32_t st = sb + (c % STAGES) * STG_B;
        const uint32_t aH = st + aoff;
        const uint32_t bH = st + TILE_B + boff;

        #pragma unroll
        for (int ks = 0; ks < 2; ks++) {
            uint32_t ah[4][4], bh[8][2];
            #pragma unroll
            for (int mi = 0; mi < 4; mi++)
                ldsm4(ah[mi], aH + mi * 1280 + ks * 32);
            #pragma unroll
            for (int j = 0; j < 4; j++) {
                uint32_t t[4];
                ldsm4(t, bH + j * 1280 + ks * 32);
                bh[2*j][0] = t[0]; bh[2*j][1] = t[1];
                bh[2*j+1][0] = t[2]; bh[2*j+1][1] = t[3];
            }
            #pragma unroll
            for (int mi = 0; mi < 4; mi++)
                #pragma unroll
                for (int ni = 0; ni < 8; ni++)
                    mma16816(acc[mi][ni], ah[mi], bh[ni]);
        }
    }

    const int fr = lane >> 2, fc = (lane & 3) * 2;
    #pragma unroll
    for (int mi = 0; mi < 4; mi++)
        #pragma unroll
        for (int ni = 0; ni < 8; ni++) {
            const int row = m0 + m0w + mi * 16 + fr;
            const int col = n0 + n0w + ni * 8 + fc;
            float* pc = acc[mi][ni];
            if (MODE == 0 || MODE == 2) {
                float2 v0 = make_float2(pc[0], pc[1]);
                float2 v1 = make_float2(pc[2], pc[3]);
                if (MODE == 2) {
                    const float b0v = bias[col], b1v = bias[col + 1];
                    v0.x += b0v; v0.y += b1v; v1.x += b0v; v1.y += b1v;
                }
                float* base = Cf + (size_t)b * sC;
                *(float2*)(base + (size_t)row * Nc + col) = v0;
                *(float2*)(base + (size_t)(row + 8) * Nc + col) = v1;
            } else if (MODE == 4) {
                const size_t i0 = (size_t)b * sC + (size_t)row * Nc + col;
                const size_t i1 = (size_t)b * sC + (size_t)(row + 8) * Nc + col;
                *(uint32_t*)(Ch + i0) = pack2(pc[0], pc[1]);
                *(uint32_t*)(Ch + i1) = pack2(pc[2], pc[3]);
            } else {
                // MODE 5: batch-folded transposed (V): [b][emb][seq]
                const size_t bb = (size_t)(col >> 11) * ((size_t)EMB * SEQL);
                const size_t i0 = bb + (size_t)row * SEQL + (col & 2047);
                const size_t i1 = i0 + (size_t)8 * SEQL;
                *(uint32_t*)(Ch + i0) = pack2(pc[0], pc[1]);
                *(uint32_t*)(Ch + i1) = pack2(pc[2], pc[3]);
            }
        }
}

// ---------------------------------------------------------------------------
// fp32 -> fp16 convert; up to 4 arrays per launch
// ---------------------------------------------------------------------------
struct ConvJob { const float* x; __half* h; };

__global__ __launch_bounds__(256)
void conv_multi(ConvJob j0, ConvJob j1, ConvJob j2, ConvJob j3, int n4)
{
    const ConvJob& j = (blockIdx.y == 0) ? j0 : (blockIdx.y == 1) ? j1
                     : (blockIdx.y == 2) ? j2 : j3;
    int i = blockIdx.x * 256 + threadIdx.x;
    if (i >= n4) return;
    float4 v = ((const float4*)j.x)[i];
    ((uint2*)j.h)[i] = make_uint2(pack2(v.x, v.y), pack2(v.z, v.w));
}

// ---------------------------------------------------------------------------
// masked softmax on fp32 E, writing fp16 probabilities
// ---------------------------------------------------------------------------
__global__ __launch_bounds__(256)
void softmax_h(const float* __restrict__ E, const int* __restrict__ mask,
               __half* __restrict__ Ph)
{
    const int row = blockIdx.x;
    const int b = row >> 11;
    const float* e = E + (size_t)row * SEQL;
    const int* m = mask + (size_t)b * SEQL * SEQL + (size_t)(row & 2047) * SEQL;
    const int t = threadIdx.x;
    const int base = t * 8;

    float v[8];
    #pragma unroll
    for (int g = 0; g < 2; g++) {
        float4 ev = *(const float4*)(e + base + g * 4);
        int4 mv = *(const int4*)(m + base + g * 4);
        v[g*4+0] = ((mv.x == 0) ? -1e20f : ev.x) * 0.03125f;
        v[g*4+1] = ((mv.y == 0) ? -1e20f : ev.y) * 0.03125f;
        v[g*4+2] = ((mv.z == 0) ? -1e20f : ev.z) * 0.03125f;
        v[g*4+3] = ((mv.w == 0) ? -1e20f : ev.w) * 0.03125f;
    }
    float mx = -3.4e38f;
    #pragma unroll
    for (int i = 0; i < 8; i++) mx = fmaxf(mx, v[i]);

    __shared__ float red[256];
    red[t] = mx;
    __syncthreads();
    for (int s = 128; s > 0; s >>= 1) {
        if (t < s) red[t] = fmaxf(red[t], red[t + s]);
        __syncthreads();
    }
    mx = red[0];
    __syncthreads();

    float sum = 0.f;
    #pragma unroll
    for (int i = 0; i < 8; i++) { v[i] = __expf(v[i] - mx); sum += v[i]; }
    red[t] = sum;
    __syncthreads();
    for (int s = 128; s > 0; s >>= 1) {
        if (t < s) red[t] += red[t + s];
        __syncthreads();
    }
    const float inv = 1.f / red[0];

    #pragma unroll
    for (int g = 0; g < 2; g++) {
        uint2 hv;
        hv.x = pack2(v[g*4+0] * inv, v[g*4+1] * inv);
        hv.y = pack2(v[g*4+2] * inv, v[g*4+3] * inv);
        ((uint2*)(Ph + (size_t)row * SEQL + base))[g] = hv;
    }
}

// ---------------------------------------------------------------------------
#define SYM(p, s) do { void* _t; cudaGetSymbolAddress(&_t, s); p = (decltype(p))_t; } while (0)

extern "C" void kernel_launch(void* const* d_in, const int* in_sizes, int n_in,
                              void* d_out, int out_size)
{
    const float* values = (const float*)d_in[0];
    const float* keys   = (const float*)d_in[1];
    const float* query  = (const float*)d_in[2];
    const int*   mask   = (const int*)  d_in[3];
    const float* Wv     = (const float*)d_in[4];
    const float* Wk     = (const float*)d_in[5];
    const float* Wq     = (const float*)d_in[6];
    const float* Wo     = (const float*)d_in[7];
    const float* bo     = (const float*)d_in[8];
    float* out = (float*)d_out;

    __half *xvh, *xkh, *xqh, *wvh, *wkh, *wqh, *woh;
    __half *qh, *kh, *vth, *ph, *oh;
    float* ge;
    SYM(xvh, g_xvh); SYM(xkh, g_xkh); SYM(xqh, g_xqh);
    SYM(wvh, g_wvh); SYM(wkh, g_wkh); SYM(wqh, g_wqh); SYM(woh, g_woh);
    SYM(qh, g_qh); SYM(kh, g_kh); SYM(vth, g_vth); SYM(ph, g_ph);
    SYM(oh, g_oh); SYM(ge, g_e);

    cudaFuncSetAttribute(hgemm<0>, cudaFuncAttributeMaxDynamicSharedMemorySize, GEMM_SMEM);
    cudaFuncSetAttribute(hgemm<2>, cudaFuncAttributeMaxDynamicSharedMemorySize, GEMM_SMEM);
    cudaFuncSetAttribute(hgemm<4>, cudaFuncAttributeMaxDynamicSharedMemorySize, GEMM_SMEM);
    cudaFuncSetAttribute(hgemm<5>, cudaFuncAttributeMaxDynamicSharedMemorySize, GEMM_SMEM);

    const int n4x = (int)(EX / 4), n4w = (int)(EW / 4);
    {
        ConvJob jv{values, xvh}, jk{keys, xkh}, jq{query, xqh};
        conv_multi<<<dim3((n4x + 255) / 256, 3, 1), 256>>>(jv, jk, jq, jq, n4x);
        ConvJob wv{Wv, wvh}, wk{Wk, wkh}, wq{Wq, wqh}, wo{Wo, woh};
        conv_multi<<<dim3((n4w + 255) / 256, 4, 1), 256>>>(wv, wk, wq, wo, n4w);
    }

    // Q = Xq @ Wq^T
    hgemm<4><<<dim3(8, 64, 1), 128, GEMM_SMEM>>>(
        xqh, wqh, EMB, 0, 0, nullptr, nullptr, 0, EMB, qh);
    // K = Xk @ Wk^T
    hgemm<4><<<dim3(8, 64, 1), 128, GEMM_SMEM>>>(
        xkh, wkh, EMB, 0, 0, nullptr, nullptr, 0, EMB, kh);
    // Vt = Wv @ Xv^T (batch-folded transposed layout)
    hgemm<5><<<dim3(64, 8, 1), 128, GEMM_SMEM>>>(
        wvh, xvh, EMB, 0, 0, nullptr, nullptr, 0, SEQL, vth);

    // E = Q @ K^T per batch (fp32)
    hgemm<0><<<dim3(16, 16, NBAT), 128, GEMM_SMEM>>>(
        qh, kh, EMB, (size_t)SEQL * EMB, (size_t)SEQL * EMB,
        ge, nullptr, (size_t)SEQL * SEQL, SEQL, nullptr);

    softmax_h<<<NBAT * SEQL, 256>>>(ge, mask, ph);

    // O = P @ Vt^T per batch
    hgemm<4><<<dim3(8, 16, NBAT), 128, GEMM_SMEM>>>(
        ph, vth, SEQL, (size_t)SEQL * SEQL, (size_t)EMB * SEQL,
        nullptr, nullptr, (size_t)SEQL * EMB, EMB, oh);

    // out = O @ Wo^T + bo (fp32)
    hgemm<2><<<dim3(8, 64, 1), 128, GEMM_SMEM>>>(
        oh, woh, EMB, 0, 0, out, bo, 0, EMB, nullptr);
}